// round 6
// baseline (speedup 1.0000x reference)
#include <cuda_runtime.h>
#include <cstdint>

#define OUT_ELE (16 * 256 * 256)

typedef unsigned long long u64;

#define PACK2(d, lo, hi) \
    asm("mov.b64 %0, {%1, %2};" : "=l"(d) : "r"(__float_as_uint(lo)), "r"(__float_as_uint(hi)))
#define UNPACK2(lo, hi, s) do { unsigned _ulo, _uhi; \
    asm("mov.b64 {%0, %1}, %2;" : "=r"(_ulo), "=r"(_uhi) : "l"(s)); \
    lo = __uint_as_float(_ulo); hi = __uint_as_float(_uhi); } while (0)
#define FMA2(d, a, b, c) \
    asm("fma.rn.f32x2 %0, %1, %2, %3;" : "=l"(d) : "l"(a), "l"(b), "l"(c))

// scratch
__device__ float g_pooled[16 * 256 * 64];           // 1 MB
__device__ float g_kv[131072 * 128];                // 64 MB: cols 0-63 = k, 64-127 = v

// ---------------------------------------------------------------------------
// K1: kv projection GEMM (+ pooled zeroing folded into first 256 blocks).
// 1024 blocks x 256 thr; block = 128 tokens x 128 cols. 3 blocks/SM target.
// Warp = 16 tokens (8 packed pairs, broadcast) x 128 cols (lane, +32, +64, +96).
// smem per 64-d chunk:
//   sp: packed x token-pairs, [64 d][65 u64] (f32 stride 130) - fill 2-way max
//   sw: weights, [64 d][129 f32]            - fill & load conflict-free
// Per warp-d-step: 8 broadcast LDS.64 + 4 LDS.32 = 12 wavefronts, 32 FMA2.
// xq staged 4+4 to cut live registers (occupancy 3 => ~85 reg budget).
// ---------------------------------------------------------------------------
#define SP_F  (64 * 130)
#define SW_RS 129
#define SMEM_PROJ ((SP_F + 64 * SW_RS) * 4)

__global__ void __launch_bounds__(256, 3) k_proj(
    const float* __restrict__ x,
    const float* __restrict__ wks,
    const float* __restrict__ wvs)
{
    extern __shared__ float sm[];
    float* sp_f = sm;                 // [64][130] f32 == [64][65] u64
    u64*   sp64 = (u64*)sp_f;
    float* sw   = sm + SP_F;          // [64][129]

    const int tid  = threadIdx.x;
    const int lane = tid & 31;
    const int w    = tid >> 5;
    const int tbase = blockIdx.x * 128;

    // folded pooled zeroing
    if (blockIdx.x < 256) {
        reinterpret_cast<float4*>(g_pooled)[blockIdx.x * 256 + tid] =
            make_float4(0.f, 0.f, 0.f, 0.f);
    }

    u64 acc[8][4];
    #pragma unroll
    for (int tp = 0; tp < 8; tp++)
        #pragma unroll
        for (int c = 0; c < 4; c++) acc[tp][c] = 0ull;

    for (int chunk = 0; chunk < 4; chunk++) {
        const int d0 = chunk * 64;

        // fill sw: warp w loads weight rows c = w*16 .. +15
        // (coalesced LDG; STS banks (lane + c) % 32 -> conflict-free)
        #pragma unroll
        for (int rr = 0; rr < 16; rr++) {
            const int c = w * 16 + rr;
            const float* wp = (c < 64 ? wks + c * 256 : wvs + (c - 64) * 256) + d0;
            sw[lane * SW_RS + c]        = wp[lane];
            sw[(32 + lane) * SW_RS + c] = wp[32 + lane];
        }
        // fill sp: pair-packed x (STS 2-way max)
        #pragma unroll
        for (int rr = 0; rr < 16; rr++) {
            const int tl = w * 16 + rr;
            const float* xp = x + (size_t)(tbase + tl) * 256 + d0;
            const int g = tl >> 1, h = tl & 1;
            sp_f[lane * 130 + g * 2 + h]        = xp[lane];
            sp_f[(32 + lane) * 130 + g * 2 + h] = xp[32 + lane];
        }
        __syncthreads();

        #pragma unroll 2
        for (int d = 0; d < 64; d++) {
            const float w0 = sw[d * SW_RS +       lane];
            const float w1 = sw[d * SW_RS +  32 + lane];
            const float w2 = sw[d * SW_RS +  64 + lane];
            const float w3 = sw[d * SW_RS +  96 + lane];
            u64 ws[4];
            PACK2(ws[0], w0, w0); PACK2(ws[1], w1, w1);
            PACK2(ws[2], w2, w2); PACK2(ws[3], w3, w3);

            // stage xq in two groups of 4 (8 live regs instead of 16)
            u64 xq[4];
            #pragma unroll
            for (int tp = 0; tp < 4; tp++)
                xq[tp] = sp64[d * 65 + w * 8 + tp];          // broadcast
            #pragma unroll
            for (int tp = 0; tp < 4; tp++) {
                FMA2(acc[tp][0], xq[tp], ws[0], acc[tp][0]);
                FMA2(acc[tp][1], xq[tp], ws[1], acc[tp][1]);
                FMA2(acc[tp][2], xq[tp], ws[2], acc[tp][2]);
                FMA2(acc[tp][3], xq[tp], ws[3], acc[tp][3]);
            }
            #pragma unroll
            for (int tp = 0; tp < 4; tp++)
                xq[tp] = sp64[d * 65 + w * 8 + 4 + tp];      // broadcast
            #pragma unroll
            for (int tp = 0; tp < 4; tp++) {
                FMA2(acc[4 + tp][0], xq[tp], ws[0], acc[4 + tp][0]);
                FMA2(acc[4 + tp][1], xq[tp], ws[1], acc[4 + tp][1]);
                FMA2(acc[4 + tp][2], xq[tp], ws[2], acc[4 + tp][2]);
                FMA2(acc[4 + tp][3], xq[tp], ws[3], acc[4 + tp][3]);
            }
        }
        __syncthreads();
    }

    // epilogue: token (w*16 + 2tp [+1]), col lane + 32k  (coalesced STG.32)
    #pragma unroll
    for (int tp = 0; tp < 8; tp++) {
        const size_t t = (size_t)tbase + w * 16 + tp * 2;
        #pragma unroll
        for (int k = 0; k < 4; k++) {
            float lo, hi;
            UNPACK2(lo, hi, acc[tp][k]);
            g_kv[t * 128       + k * 32 + lane] = lo;
            g_kv[(t + 1) * 128 + k * 32 + lane] = hi;
        }
    }
}

// ---------------------------------------------------------------------------
// K2: attn + argmax + one-hot + v scatter.  2048 blocks x 256 thr, 64 tokens.
// Warp = 8 tokens; A[t][i] = (attn[i*32+lane], attn[128+i*32+lane]).
// smem: ksq [64 tok][33 quads] - k duplicated quads (k_j,k_j,k_j1,k_j1),
//       consumed via ONE broadcast LDS.128 per (t, j-pair): 1 wf, 0 movs.
//       q2p [64 j][129 u64] (q row-pairs, loads conflict-free 2-wf).
// Per 2-j step per warp: 8 LDS.64 q (16 wf) + 8 bcast LDS.128 (8 wf), 64 FMA2.
// ---------------------------------------------------------------------------
#define KSQ_QS 33                      // quads per token row (32 + 1 pad)
#define KSQ_BYTES (64 * KSQ_QS * 16)   // 33792 B, 16B aligned at smem base
#define QRS 129                        // u64 row stride
#define SMEM_ATTN (KSQ_BYTES + 64 * QRS * 8)

__global__ void __launch_bounds__(256, 2) k_attn(
    const float* __restrict__ q,
    float* __restrict__ hard)
{
    extern __shared__ char smraw[];
    float4* ksq = (float4*)smraw;               // [64 tok][33] dup quads
    u64*    q2p = (u64*)(smraw + KSQ_BYTES);    // [64 j][129]
    float*  q2f = (float*)q2p;

    const int tid  = threadIdx.x;
    const int lane = tid & 31;
    const int w    = tid >> 5;
    const int tblk = blockIdx.x * 64;

    // fill q2p: q2p[j][rr] = (q[rr][j], q[rr+128][j])   (STS 2-way max)
    for (int idx = tid; idx < 256 * 64; idx += 256) {
        const int row = idx >> 6, j = idx & 63;
        const int h = row >> 7, rr = row & 127;
        q2f[(j * QRS + rr) * 2 + h] = q[idx];
    }
    // fill ksq: lane handles j-pair = lane for token tl (coalesced LDG.64,
    // STS.128 phase banks 4*lane -> conflict-free)
    #pragma unroll
    for (int rr = 0; rr < 8; rr++) {
        const int tl = w * 8 + rr;
        const float2 kk = *(const float2*)(g_kv + (size_t)(tblk + tl) * 128 + 2 * lane);
        ksq[tl * KSQ_QS + lane] = make_float4(kk.x, kk.x, kk.y, kk.y);
    }
    __syncthreads();

    u64 A[8][4];
    #pragma unroll
    for (int t = 0; t < 8; t++)
        #pragma unroll
        for (int i = 0; i < 4; i++) A[t][i] = 0ull;

    const ulonglong2* ksq2 = (const ulonglong2*)ksq;

    for (int j = 0; j < 64; j += 2) {
        u64 qv0[4], qv1[4];
        #pragma unroll
        for (int i = 0; i < 4; i++) {
            qv0[i] = q2p[j * QRS + i * 32 + lane];
            qv1[i] = q2p[(j + 1) * QRS + i * 32 + lane];
        }
        #pragma unroll
        for (int t = 0; t < 8; t++) {
            // one broadcast LDS.128: (k_j, k_j, k_{j+1}, k_{j+1})
            const ulonglong2 kq = ksq2[(w * 8 + t) * KSQ_QS + (j >> 1)];
            FMA2(A[t][0], kq.x, qv0[0], A[t][0]);
            FMA2(A[t][1], kq.x, qv0[1], A[t][1]);
            FMA2(A[t][2], kq.x, qv0[2], A[t][2]);
            FMA2(A[t][3], kq.x, qv0[3], A[t][3]);
            FMA2(A[t][0], kq.y, qv1[0], A[t][0]);
            FMA2(A[t][1], kq.y, qv1[1], A[t][1]);
            FMA2(A[t][2], kq.y, qv1[2], A[t][2]);
            FMA2(A[t][3], kq.y, qv1[3], A[t][3]);
        }
    }

    // epilogue
    #pragma unroll
    for (int t = 0; t < 8; t++) {
        const int tglob = tblk + w * 8 + t;
        float lo[4], hi[4];
        #pragma unroll
        for (int i = 0; i < 4; i++) UNPACK2(lo[i], hi[i], A[t][i]);

        float bv = lo[0]; int bi = lane;
        #pragma unroll
        for (int i = 1; i < 4; i++)
            if (lo[i] > bv) { bv = lo[i]; bi = i * 32 + lane; }
        #pragma unroll
        for (int i = 0; i < 4; i++)
            if (hi[i] > bv) { bv = hi[i]; bi = 128 + i * 32 + lane; }
        #pragma unroll
        for (int off = 16; off > 0; off >>= 1) {
            const float ov = __shfl_xor_sync(0xffffffffu, bv, off);
            const int   oi = __shfl_xor_sync(0xffffffffu, bi, off);
            if (ov > bv || (ov == bv && oi < bi)) { bv = ov; bi = oi; }
        }

        // one-hot row
        float4* hp = (float4*)(hard + (size_t)tglob * 256);
        const int c0 = lane * 8;
        float4 o0, o1;
        o0.x = (c0 + 0 == bi) ? 1.f : 0.f;  o0.y = (c0 + 1 == bi) ? 1.f : 0.f;
        o0.z = (c0 + 2 == bi) ? 1.f : 0.f;  o0.w = (c0 + 3 == bi) ? 1.f : 0.f;
        o1.x = (c0 + 4 == bi) ? 1.f : 0.f;  o1.y = (c0 + 5 == bi) ? 1.f : 0.f;
        o1.z = (c0 + 6 == bi) ? 1.f : 0.f;  o1.w = (c0 + 7 == bi) ? 1.f : 0.f;
        hp[lane * 2]     = o0;
        hp[lane * 2 + 1] = o1;

        // scatter v
        const float* vp = g_kv + (size_t)tglob * 128 + 64;
        const float v0 = vp[lane], v1 = vp[32 + lane];
        const int b = tglob >> 13;
        float* pp = g_pooled + (size_t)(b * 256 + bi) * 64;
        atomicAdd(pp + lane,      v0);
        atomicAdd(pp + 32 + lane, v1);
    }
}

// ---------------------------------------------------------------------------
// K3: out[b,q,d] = sum_v pooled[b,q,v] * w_fc[d,v]
// 512 blocks x 256 thr, 8 rows/block. Weights in registers, 8 row chains.
// ---------------------------------------------------------------------------
#define WF_RS 68
#define SMEM_FC ((256 * WF_RS + 8 * 64) * 4)

__global__ void __launch_bounds__(256, 2) k_fc(
    const float* __restrict__ wfc,
    float* __restrict__ out)
{
    extern __shared__ float sm[];
    float* s_wf = sm;                  // [256][68]
    float* s_p  = sm + 256 * WF_RS;    // [8][64]

    const int tid = threadIdx.x;
    for (int idx = tid; idx < 256 * 64; idx += 256) {
        const int d = idx >> 6, v = idx & 63;
        s_wf[d * WF_RS + v] = wfc[idx];
    }
    const int r0 = blockIdx.x * 8;
    for (int idx = tid; idx < 8 * 64; idx += 256)
        s_p[idx] = g_pooled[(size_t)r0 * 64 + idx];
    __syncthreads();

    const int d = tid;
    float4 W[16];
    #pragma unroll
    for (int m = 0; m < 16; m++)
        W[m] = *(const float4*)&s_wf[d * WF_RS + m * 4];

    float acc[8];
    #pragma unroll
    for (int r = 0; r < 8; r++) acc[r] = 0.f;

    #pragma unroll
    for (int m = 0; m < 16; m++) {
        #pragma unroll
        for (int r = 0; r < 8; r++) {
            const float4 p = *(const float4*)&s_p[r * 64 + m * 4];  // broadcast
            acc[r] = fmaf(p.x, W[m].x, acc[r]);
            acc[r] = fmaf(p.y, W[m].y, acc[r]);
            acc[r] = fmaf(p.z, W[m].z, acc[r]);
            acc[r] = fmaf(p.w, W[m].w, acc[r]);
        }
    }
    #pragma unroll
    for (int r = 0; r < 8; r++)
        out[(size_t)(r0 + r) * 256 + d] = acc[r];
}

// ---------------------------------------------------------------------------
extern "C" void kernel_launch(void* const* d_in, const int* in_sizes, int n_in,
                              void* d_out, int out_size)
{
    const float* x   = (const float*)d_in[0];
    const float* q   = (const float*)d_in[1];
    const float* wks = (const float*)d_in[2];
    const float* wvs = (const float*)d_in[3];
    const float* wfc = (const float*)d_in[4];

    float* out  = (float*)d_out;
    float* hard = out + OUT_ELE;

    static bool attr_done = false;
    if (!attr_done) {
        cudaFuncSetAttribute(k_proj, cudaFuncAttributeMaxDynamicSharedMemorySize, SMEM_PROJ);
        cudaFuncSetAttribute(k_attn, cudaFuncAttributeMaxDynamicSharedMemorySize, SMEM_ATTN);
        cudaFuncSetAttribute(k_fc,   cudaFuncAttributeMaxDynamicSharedMemorySize, SMEM_FC);
        attr_done = true;
    }

    k_proj<<<1024, 256, SMEM_PROJ>>>(x, wks, wvs);
    k_attn<<<2048, 256, SMEM_ATTN>>>(q, hard);
    k_fc<<<512, 256, SMEM_FC>>>(wfc, out);
}

// round 8
// speedup vs baseline: 1.3079x; 1.3079x over previous
#include <cuda_runtime.h>
#include <cstdint>

#define OUT_ELE (16 * 256 * 256)

typedef unsigned long long u64;

#define PACK2(d, lo, hi) \
    asm("mov.b64 %0, {%1, %2};" : "=l"(d) : "r"(__float_as_uint(lo)), "r"(__float_as_uint(hi)))
#define UNPACK2(lo, hi, s) do { unsigned _ulo, _uhi; \
    asm("mov.b64 {%0, %1}, %2;" : "=r"(_ulo), "=r"(_uhi) : "l"(s)); \
    lo = __uint_as_float(_ulo); hi = __uint_as_float(_uhi); } while (0)
#define FMA2(d, a, b, c) \
    asm("fma.rn.f32x2 %0, %1, %2, %3;" : "=l"(d) : "l"(a), "l"(b), "l"(c))

// scratch
__device__ float g_pooled[16 * 256 * 64];           // 1 MB
__device__ float g_kv[131072 * 128];                // 64 MB: cols 0-63 = k, 64-127 = v

// ---------------------------------------------------------------------------
// K1: kv projection GEMM (+ pooled zeroing folded into first 256 blocks).
// == R4 version, measured 205us, fma=61.5%, regs=128, 2 blocks/SM ==
// 1024 blocks x 256 thr; block = 128 tokens x 128 cols.
// Per warp-d-step: 8 broadcast LDS.64 + 4 LDS.32 = 12 wavefronts, 32 FMA2.
// ---------------------------------------------------------------------------
#define SP_F  (64 * 130)
#define SW_RS 129
#define SMEM_PROJ ((SP_F + 64 * SW_RS) * 4)

__global__ void __launch_bounds__(256, 2) k_proj(
    const float* __restrict__ x,
    const float* __restrict__ wks,
    const float* __restrict__ wvs)
{
    extern __shared__ float sm[];
    float* sp_f = sm;                 // [64][130] f32 == [64][65] u64
    u64*   sp64 = (u64*)sp_f;
    float* sw   = sm + SP_F;          // [64][129]

    const int tid  = threadIdx.x;
    const int lane = tid & 31;
    const int w    = tid >> 5;
    const int tbase = blockIdx.x * 128;

    // folded pooled zeroing (k_attn, which reads it, runs in a later launch)
    if (blockIdx.x < 256) {
        reinterpret_cast<float4*>(g_pooled)[blockIdx.x * 256 + tid] =
            make_float4(0.f, 0.f, 0.f, 0.f);
    }

    u64 acc[8][4];
    #pragma unroll
    for (int tp = 0; tp < 8; tp++)
        #pragma unroll
        for (int c = 0; c < 4; c++) acc[tp][c] = 0ull;

    for (int chunk = 0; chunk < 4; chunk++) {
        const int d0 = chunk * 64;

        // fill sw: warp w loads weight rows c = w*16 .. +15 (coalesced LDG,
        // STS banks (lane + c) % 32 -> conflict-free)
        #pragma unroll
        for (int rr = 0; rr < 16; rr++) {
            const int c = w * 16 + rr;
            const float* wp = (c < 64 ? wks + c * 256 : wvs + (c - 64) * 256) + d0;
            sw[lane * SW_RS + c]        = wp[lane];
            sw[(32 + lane) * SW_RS + c] = wp[32 + lane];
        }
        // fill sp: pair-packed x (STS 2-way max)
        #pragma unroll
        for (int rr = 0; rr < 16; rr++) {
            const int tl = w * 16 + rr;
            const float* xp = x + (size_t)(tbase + tl) * 256 + d0;
            const int g = tl >> 1, h = tl & 1;
            sp_f[lane * 130 + g * 2 + h]        = xp[lane];
            sp_f[(32 + lane) * 130 + g * 2 + h] = xp[32 + lane];
        }
        __syncthreads();

        #pragma unroll 2
        for (int d = 0; d < 64; d++) {
            u64 xq[8];
            #pragma unroll
            for (int tp = 0; tp < 8; tp++)
                xq[tp] = sp64[d * 65 + w * 8 + tp];          // broadcast LDS.64
            const float w0 = sw[d * SW_RS +       lane];
            const float w1 = sw[d * SW_RS +  32 + lane];
            const float w2 = sw[d * SW_RS +  64 + lane];
            const float w3 = sw[d * SW_RS +  96 + lane];
            u64 ws[4];
            PACK2(ws[0], w0, w0); PACK2(ws[1], w1, w1);
            PACK2(ws[2], w2, w2); PACK2(ws[3], w3, w3);
            #pragma unroll
            for (int tp = 0; tp < 8; tp++) {
                FMA2(acc[tp][0], xq[tp], ws[0], acc[tp][0]);
                FMA2(acc[tp][1], xq[tp], ws[1], acc[tp][1]);
                FMA2(acc[tp][2], xq[tp], ws[2], acc[tp][2]);
                FMA2(acc[tp][3], xq[tp], ws[3], acc[tp][3]);
            }
        }
        __syncthreads();
    }

    // epilogue: token (w*16 + 2tp [+1]), col lane + 32k  (coalesced STG.32)
    #pragma unroll
    for (int tp = 0; tp < 8; tp++) {
        const size_t t = (size_t)tbase + w * 16 + tp * 2;
        #pragma unroll
        for (int k = 0; k < 4; k++) {
            float lo, hi;
            UNPACK2(lo, hi, acc[tp][k]);
            g_kv[t * 128       + k * 32 + lane] = lo;
            g_kv[(t + 1) * 128 + k * 32 + lane] = hi;
        }
    }
}

// ---------------------------------------------------------------------------
// K2: attn + argmax + one-hot + v scatter.  == R3 version (best measured) ==
// 2048 blocks x 256 thr, 64 tokens. Warp = 8 tokens.
// smem: q2p [64 j][129 u64] (q row-pairs), ks2 [64 tok][66 f32] transposed k,
//       consumed as j-pair broadcast LDS.64.
// ---------------------------------------------------------------------------
#define QRS 129                       // u64 row stride
#define KS_RS 66
#define SMEM_ATTN ((64 * QRS * 2 + 64 * KS_RS) * 4)

__global__ void __launch_bounds__(256, 2) k_attn(
    const float* __restrict__ q,
    float* __restrict__ hard)
{
    extern __shared__ float sm[];
    u64*   q2p = (u64*)sm;             // [64][QRS]
    float* q2f = sm;                   // f32 view
    float* ks2 = sm + 64 * QRS * 2;    // [64 tok][66]
    u64*   ks64 = (u64*)ks2;           // [64 tok][33]

    const int tid  = threadIdx.x;
    const int lane = tid & 31;
    const int w    = tid >> 5;
    const int tblk = blockIdx.x * 64;

    // fill q2p: q2p[j][rr] = (q[rr][j], q[rr+128][j])   (STS 2-way max)
    for (int idx = tid; idx < 256 * 64; idx += 256) {
        const int row = idx >> 6, j = idx & 63;
        const int h = row >> 7, rr = row & 127;
        q2f[(j * QRS + rr) * 2 + h] = q[idx];
    }
    // fill ks2 (transposed): ks2[tl][j] = k[tblk+tl][j]
    #pragma unroll
    for (int rr = 0; rr < 8; rr++) {
        const int tl = w * 8 + rr;
        const float* kp = g_kv + (size_t)(tblk + tl) * 128;
        ks2[tl * KS_RS + lane]      = kp[lane];
        ks2[tl * KS_RS + 32 + lane] = kp[32 + lane];
    }
    __syncthreads();

    u64 A[8][4];
    #pragma unroll
    for (int t = 0; t < 8; t++)
        #pragma unroll
        for (int i = 0; i < 4; i++) A[t][i] = 0ull;

    for (int j = 0; j < 64; j += 2) {
        u64 qv0[4], qv1[4];
        #pragma unroll
        for (int i = 0; i < 4; i++) {
            qv0[i] = q2p[j * QRS + i * 32 + lane];
            qv1[i] = q2p[(j + 1) * QRS + i * 32 + lane];
        }
        #pragma unroll
        for (int t = 0; t < 8; t++) {
            const u64 kp2 = ks64[(w * 8 + t) * 33 + (j >> 1)];  // bcast LDS.64
            float ka, kb;
            UNPACK2(ka, kb, kp2);
            u64 kaa, kbb;
            PACK2(kaa, ka, ka); PACK2(kbb, kb, kb);
            FMA2(A[t][0], kaa, qv0[0], A[t][0]);
            FMA2(A[t][1], kaa, qv0[1], A[t][1]);
            FMA2(A[t][2], kaa, qv0[2], A[t][2]);
            FMA2(A[t][3], kaa, qv0[3], A[t][3]);
            FMA2(A[t][0], kbb, qv1[0], A[t][0]);
            FMA2(A[t][1], kbb, qv1[1], A[t][1]);
            FMA2(A[t][2], kbb, qv1[2], A[t][2]);
            FMA2(A[t][3], kbb, qv1[3], A[t][3]);
        }
    }

    // epilogue
    #pragma unroll
    for (int t = 0; t < 8; t++) {
        const int tglob = tblk + w * 8 + t;
        float lo[4], hi[4];
        #pragma unroll
        for (int i = 0; i < 4; i++) UNPACK2(lo[i], hi[i], A[t][i]);

        float bv = lo[0]; int bi = lane;
        #pragma unroll
        for (int i = 1; i < 4; i++)
            if (lo[i] > bv) { bv = lo[i]; bi = i * 32 + lane; }
        #pragma unroll
        for (int i = 0; i < 4; i++)
            if (hi[i] > bv) { bv = hi[i]; bi = 128 + i * 32 + lane; }
        #pragma unroll
        for (int off = 16; off > 0; off >>= 1) {
            const float ov = __shfl_xor_sync(0xffffffffu, bv, off);
            const int   oi = __shfl_xor_sync(0xffffffffu, bi, off);
            if (ov > bv || (ov == bv && oi < bi)) { bv = ov; bi = oi; }
        }

        // one-hot row
        float4* hp = (float4*)(hard + (size_t)tglob * 256);
        const int c0 = lane * 8;
        float4 o0, o1;
        o0.x = (c0 + 0 == bi) ? 1.f : 0.f;  o0.y = (c0 + 1 == bi) ? 1.f : 0.f;
        o0.z = (c0 + 2 == bi) ? 1.f : 0.f;  o0.w = (c0 + 3 == bi) ? 1.f : 0.f;
        o1.x = (c0 + 4 == bi) ? 1.f : 0.f;  o1.y = (c0 + 5 == bi) ? 1.f : 0.f;
        o1.z = (c0 + 6 == bi) ? 1.f : 0.f;  o1.w = (c0 + 7 == bi) ? 1.f : 0.f;
        hp[lane * 2]     = o0;
        hp[lane * 2 + 1] = o1;

        // scatter v
        const float* vp = g_kv + (size_t)tglob * 128 + 64;
        const float v0 = vp[lane], v1 = vp[32 + lane];
        const int b = tglob >> 13;
        float* pp = g_pooled + (size_t)(b * 256 + bi) * 64;
        atomicAdd(pp + lane,      v0);
        atomicAdd(pp + 32 + lane, v1);
    }
}

// ---------------------------------------------------------------------------
// K3: out[b,q,d] = sum_v pooled[b,q,v] * w_fc[d,v]
// 512 blocks x 256 thr, 8 rows/block. Weights in registers, 8 row chains.
// ---------------------------------------------------------------------------
#define WF_RS 68
#define SMEM_FC ((256 * WF_RS + 8 * 64) * 4)

__global__ void __launch_bounds__(256, 2) k_fc(
    const float* __restrict__ wfc,
    float* __restrict__ out)
{
    extern __shared__ float sm[];
    float* s_wf = sm;                  // [256][68]
    float* s_p  = sm + 256 * WF_RS;    // [8][64]

    const int tid = threadIdx.x;
    for (int idx = tid; idx < 256 * 64; idx += 256) {
        const int d = idx >> 6, v = idx & 63;
        s_wf[d * WF_RS + v] = wfc[idx];
    }
    const int r0 = blockIdx.x * 8;
    for (int idx = tid; idx < 8 * 64; idx += 256)
        s_p[idx] = g_pooled[(size_t)r0 * 64 + idx];
    __syncthreads();

    const int d = tid;
    float4 W[16];
    #pragma unroll
    for (int m = 0; m < 16; m++)
        W[m] = *(const float4*)&s_wf[d * WF_RS + m * 4];

    float acc[8];
    #pragma unroll
    for (int r = 0; r < 8; r++) acc[r] = 0.f;

    #pragma unroll
    for (int m = 0; m < 16; m++) {
        #pragma unroll
        for (int r = 0; r < 8; r++) {
            const float4 p = *(const float4*)&s_p[r * 64 + m * 4];  // broadcast
            acc[r] = fmaf(p.x, W[m].x, acc[r]);
            acc[r] = fmaf(p.y, W[m].y, acc[r]);
            acc[r] = fmaf(p.z, W[m].z, acc[r]);
            acc[r] = fmaf(p.w, W[m].w, acc[r]);
        }
    }
    #pragma unroll
    for (int r = 0; r < 8; r++)
        out[(size_t)(r0 + r) * 256 + d] = acc[r];
}

// ---------------------------------------------------------------------------
extern "C" void kernel_launch(void* const* d_in, const int* in_sizes, int n_in,
                              void* d_out, int out_size)
{
    const float* x   = (const float*)d_in[0];
    const float* q   = (const float*)d_in[1];
    const float* wks = (const float*)d_in[2];
    const float* wvs = (const float*)d_in[3];
    const float* wfc = (const float*)d_in[4];

    float* out  = (float*)d_out;
    float* hard = out + OUT_ELE;

    static bool attr_done = false;
    if (!attr_done) {
        cudaFuncSetAttribute(k_proj, cudaFuncAttributeMaxDynamicSharedMemorySize, SMEM_PROJ);
        cudaFuncSetAttribute(k_attn, cudaFuncAttributeMaxDynamicSharedMemorySize, SMEM_ATTN);
        cudaFuncSetAttribute(k_fc,   cudaFuncAttributeMaxDynamicSharedMemorySize, SMEM_FC);
        attr_done = true;
    }

    k_proj<<<1024, 256, SMEM_PROJ>>>(x, wks, wvs);
    k_attn<<<2048, 256, SMEM_ATTN>>>(q, hard);
    k_fc<<<512, 256, SMEM_FC>>>(wfc, out);
}

// round 12
// speedup vs baseline: 1.3881x; 1.0614x over previous
#include <cuda_runtime.h>
#include <cstdint>

#define OUT_ELE (16 * 256 * 256)

typedef unsigned long long u64;

#define PACK2(d, lo, hi) \
    asm("mov.b64 %0, {%1, %2};" : "=l"(d) : "r"(__float_as_uint(lo)), "r"(__float_as_uint(hi)))
#define UNPACK2(lo, hi, s) do { unsigned _ulo, _uhi; \
    asm("mov.b64 {%0, %1}, %2;" : "=r"(_ulo), "=r"(_uhi) : "l"(s)); \
    lo = __uint_as_float(_ulo); hi = __uint_as_float(_uhi); } while (0)
#define FMA2(d, a, b, c) \
    asm("fma.rn.f32x2 %0, %1, %2, %3;" : "=l"(d) : "l"(a), "l"(b), "l"(c))

// scratch
__device__ float g_pooled[16 * 256 * 64];           // 1 MB
__device__ float g_kv[131072 * 128];                // 64 MB: cols 0-63 = k, 64-127 = v
__device__ float g_wt[4 * 64 * 129];                // per-chunk weight smem images
__device__ u64   g_qp[64 * 129];                    // packed-q smem image

// ---------------------------------------------------------------------------
// K0: pack weights + q into exact smem-image layouts (one launch, ~4us).
//   g_wt[chunk][d][c] = (c<64 ? wks[c][chunk*64+d] : wvs[c-64][chunk*64+d])
//   g_qp[j][rr]       = (q[rr][j], q[rr+128][j])   (rr<128; pad slot = 0)
// ---------------------------------------------------------------------------
__global__ void __launch_bounds__(256) k_pack(
    const float* __restrict__ q,
    const float* __restrict__ wks,
    const float* __restrict__ wvs)
{
    const int i = blockIdx.x * 256 + threadIdx.x;
    if (i < 4 * 64 * 129) {
        const int chunk = i / 8256, rem = i % 8256, d = rem / 129, c = rem % 129;
        float val = 0.f;
        if (c < 128)
            val = (c < 64) ? wks[c * 256 + chunk * 64 + d]
                           : wvs[(c - 64) * 256 + chunk * 64 + d];
        g_wt[i] = val;
    }
    if (i < 64 * 129) {
        const int j = i / 129, rr = i % 129;
        u64 val = 0ull;
        if (rr < 128) PACK2(val, q[rr * 64 + j], q[(rr + 128) * 64 + j]);
        g_qp[i] = val;
    }
}

// ---------------------------------------------------------------------------
// K1: kv projection GEMM (+ pooled zeroing folded into first 256 blocks).
// Main loop identical to the measured 204us version; weight fill is a linear
// float4 memcpy of the precomputed smem image (no scattered transpose).
// ---------------------------------------------------------------------------
#define SP_F  (64 * 130)
#define SW_RS 129
#define SMEM_PROJ ((SP_F + 64 * SW_RS) * 4)

__global__ void __launch_bounds__(256, 2) k_proj(
    const float* __restrict__ x)
{
    extern __shared__ float sm[];
    float* sp_f = sm;                 // [64][130] f32 == [64][65] u64
    u64*   sp64 = (u64*)sp_f;
    float* sw   = sm + SP_F;          // [64][129]  (16B-aligned: SP_F*4 = 33280)

    const int tid  = threadIdx.x;
    const int lane = tid & 31;
    const int w    = tid >> 5;
    const int tbase = blockIdx.x * 128;

    // folded pooled zeroing (k_attn, which reads it, runs in a later launch)
    if (blockIdx.x < 256) {
        reinterpret_cast<float4*>(g_pooled)[blockIdx.x * 256 + tid] =
            make_float4(0.f, 0.f, 0.f, 0.f);
    }

    u64 acc[8][4];
    #pragma unroll
    for (int tp = 0; tp < 8; tp++)
        #pragma unroll
        for (int c = 0; c < 4; c++) acc[tp][c] = 0ull;

    for (int chunk = 0; chunk < 4; chunk++) {
        const int d0 = chunk * 64;

        // fill sw: linear float4 copy of the image (2064 float4, coalesced,
        // conflict-free STS.128)
        {
            const float4* wsrc = (const float4*)(g_wt + chunk * 8256);
            float4* wdst = (float4*)sw;
            #pragma unroll
            for (int it = 0; it < 9; it++) {
                const int i = it * 256 + tid;
                if (i < 2064) wdst[i] = wsrc[i];
            }
        }
        // fill sp: pair-packed x (STS 2-way max)
        #pragma unroll
        for (int rr = 0; rr < 16; rr++) {
            const int tl = w * 16 + rr;
            const float* xp = x + (size_t)(tbase + tl) * 256 + d0;
            const int g = tl >> 1, h = tl & 1;
            sp_f[lane * 130 + g * 2 + h]        = xp[lane];
            sp_f[(32 + lane) * 130 + g * 2 + h] = xp[32 + lane];
        }
        __syncthreads();

        #pragma unroll 2
        for (int d = 0; d < 64; d++) {
            u64 xq[8];
            #pragma unroll
            for (int tp = 0; tp < 8; tp++)
                xq[tp] = sp64[d * 65 + w * 8 + tp];          // broadcast LDS.64
            const float w0 = sw[d * SW_RS +       lane];
            const float w1 = sw[d * SW_RS +  32 + lane];
            const float w2 = sw[d * SW_RS +  64 + lane];
            const float w3 = sw[d * SW_RS +  96 + lane];
            u64 ws[4];
            PACK2(ws[0], w0, w0); PACK2(ws[1], w1, w1);
            PACK2(ws[2], w2, w2); PACK2(ws[3], w3, w3);
            #pragma unroll
            for (int tp = 0; tp < 8; tp++) {
                FMA2(acc[tp][0], xq[tp], ws[0], acc[tp][0]);
                FMA2(acc[tp][1], xq[tp], ws[1], acc[tp][1]);
                FMA2(acc[tp][2], xq[tp], ws[2], acc[tp][2]);
                FMA2(acc[tp][3], xq[tp], ws[3], acc[tp][3]);
            }
        }
        __syncthreads();
    }

    // epilogue: token (w*16 + 2tp [+1]), col lane + 32k  (coalesced STG.32)
    #pragma unroll
    for (int tp = 0; tp < 8; tp++) {
        const size_t t = (size_t)tbase + w * 16 + tp * 2;
        #pragma unroll
        for (int k = 0; k < 4; k++) {
            float lo, hi;
            UNPACK2(lo, hi, acc[tp][k]);
            g_kv[t * 128       + k * 32 + lane] = lo;
            g_kv[(t + 1) * 128 + k * 32 + lane] = hi;
        }
    }
}

// ---------------------------------------------------------------------------
// K2: attn + argmax + one-hot + v scatter.  Main loop identical to R8;
// q fill is a linear float4 memcpy of the precomputed packed image.
// ---------------------------------------------------------------------------
#define QRS 129                       // u64 row stride
#define KS_RS 66
#define SMEM_ATTN ((64 * QRS * 2 + 64 * KS_RS) * 4)

__global__ void __launch_bounds__(256, 2) k_attn(
    float* __restrict__ hard)
{
    extern __shared__ float sm[];
    u64*   q2p = (u64*)sm;             // [64][QRS]
    float* ks2 = sm + 64 * QRS * 2;    // [64 tok][66]  (offset 66048B, 16B-aligned)
    u64*   ks64 = (u64*)ks2;           // [64 tok][33]

    const int tid  = threadIdx.x;
    const int lane = tid & 31;
    const int w    = tid >> 5;
    const int tblk = blockIdx.x * 64;

    // fill q2p: linear float4 copy of packed image (4128 float4, coalesced,
    // conflict-free STS.128; image is L2-resident across 2048 blocks)
    {
        const float4* qsrc = (const float4*)g_qp;
        float4* qdst = (float4*)q2p;
        #pragma unroll
        for (int it = 0; it < 17; it++) {
            const int i = it * 256 + tid;
            if (i < 4128) qdst[i] = qsrc[i];
        }
    }
    // fill ks2 (transposed): ks2[tl][j] = k[tblk+tl][j]
    #pragma unroll
    for (int rr = 0; rr < 8; rr++) {
        const int tl = w * 8 + rr;
        const float* kp = g_kv + (size_t)(tblk + tl) * 128;
        ks2[tl * KS_RS + lane]      = kp[lane];
        ks2[tl * KS_RS + 32 + lane] = kp[32 + lane];
    }
    __syncthreads();

    u64 A[8][4];
    #pragma unroll
    for (int t = 0; t < 8; t++)
        #pragma unroll
        for (int i = 0; i < 4; i++) A[t][i] = 0ull;

    for (int j = 0; j < 64; j += 2) {
        u64 qv0[4], qv1[4];
        #pragma unroll
        for (int i = 0; i < 4; i++) {
            qv0[i] = q2p[j * QRS + i * 32 + lane];
            qv1[i] = q2p[(j + 1) * QRS + i * 32 + lane];
        }
        #pragma unroll
        for (int t = 0; t < 8; t++) {
            const u64 kp2 = ks64[(w * 8 + t) * 33 + (j >> 1)];  // bcast LDS.64
            float ka, kb;
            UNPACK2(ka, kb, kp2);
            u64 kaa, kbb;
            PACK2(kaa, ka, ka); PACK2(kbb, kb, kb);
            FMA2(A[t][0], kaa, qv0[0], A[t][0]);
            FMA2(A[t][1], kaa, qv0[1], A[t][1]);
            FMA2(A[t][2], kaa, qv0[2], A[t][2]);
            FMA2(A[t][3], kaa, qv0[3], A[t][3]);
            FMA2(A[t][0], kbb, qv1[0], A[t][0]);
            FMA2(A[t][1], kbb, qv1[1], A[t][1]);
            FMA2(A[t][2], kbb, qv1[2], A[t][2]);
            FMA2(A[t][3], kbb, qv1[3], A[t][3]);
        }
    }

    // epilogue
    #pragma unroll
    for (int t = 0; t < 8; t++) {
        const int tglob = tblk + w * 8 + t;
        float lo[4], hi[4];
        #pragma unroll
        for (int i = 0; i < 4; i++) UNPACK2(lo[i], hi[i], A[t][i]);

        float bv = lo[0]; int bi = lane;
        #pragma unroll
        for (int i = 1; i < 4; i++)
            if (lo[i] > bv) { bv = lo[i]; bi = i * 32 + lane; }
        #pragma unroll
        for (int i = 0; i < 4; i++)
            if (hi[i] > bv) { bv = hi[i]; bi = 128 + i * 32 + lane; }
        #pragma unroll
        for (int off = 16; off > 0; off >>= 1) {
            const float ov = __shfl_xor_sync(0xffffffffu, bv, off);
            const int   oi = __shfl_xor_sync(0xffffffffu, bi, off);
            if (ov > bv || (ov == bv && oi < bi)) { bv = ov; bi = oi; }
        }

        // one-hot row
        float4* hp = (float4*)(hard + (size_t)tglob * 256);
        const int c0 = lane * 8;
        float4 o0, o1;
        o0.x = (c0 + 0 == bi) ? 1.f : 0.f;  o0.y = (c0 + 1 == bi) ? 1.f : 0.f;
        o0.z = (c0 + 2 == bi) ? 1.f : 0.f;  o0.w = (c0 + 3 == bi) ? 1.f : 0.f;
        o1.x = (c0 + 4 == bi) ? 1.f : 0.f;  o1.y = (c0 + 5 == bi) ? 1.f : 0.f;
        o1.z = (c0 + 6 == bi) ? 1.f : 0.f;  o1.w = (c0 + 7 == bi) ? 1.f : 0.f;
        hp[lane * 2]     = o0;
        hp[lane * 2 + 1] = o1;

        // scatter v
        const float* vp = g_kv + (size_t)tglob * 128 + 64;
        const float v0 = vp[lane], v1 = vp[32 + lane];
        const int b = tglob >> 13;
        float* pp = g_pooled + (size_t)(b * 256 + bi) * 64;
        atomicAdd(pp + lane,      v0);
        atomicAdd(pp + 32 + lane, v1);
    }
}

// ---------------------------------------------------------------------------
// K3: out[b,q,d] = sum_v pooled[b,q,v] * w_fc[d,v]
// 512 blocks x 256 thr, 8 rows/block. Weights in registers, 8 row chains.
// ---------------------------------------------------------------------------
#define WF_RS 68
#define SMEM_FC ((256 * WF_RS + 8 * 64) * 4)

__global__ void __launch_bounds__(256, 2) k_fc(
    const float* __restrict__ wfc,
    float* __restrict__ out)
{
    extern __shared__ float sm[];
    float* s_wf = sm;                  // [256][68]
    float* s_p  = sm + 256 * WF_RS;    // [8][64]

    const int tid = threadIdx.x;
    for (int idx = tid; idx < 256 * 64; idx += 256) {
        const int d = idx >> 6, v = idx & 63;
        s_wf[d * WF_RS + v] = wfc[idx];
    }
    const int r0 = blockIdx.x * 8;
    for (int idx = tid; idx < 8 * 64; idx += 256)
        s_p[idx] = g_pooled[(size_t)r0 * 64 + idx];
    __syncthreads();

    const int d = tid;
    float4 W[16];
    #pragma unroll
    for (int m = 0; m < 16; m++)
        W[m] = *(const float4*)&s_wf[d * WF_RS + m * 4];

    float acc[8];
    #pragma unroll
    for (int r = 0; r < 8; r++) acc[r] = 0.f;

    #pragma unroll
    for (int m = 0; m < 16; m++) {
        #pragma unroll
        for (int r = 0; r < 8; r++) {
            const float4 p = *(const float4*)&s_p[r * 64 + m * 4];  // broadcast
            acc[r] = fmaf(p.x, W[m].x, acc[r]);
            acc[r] = fmaf(p.y, W[m].y, acc[r]);
            acc[r] = fmaf(p.z, W[m].z, acc[r]);
            acc[r] = fmaf(p.w, W[m].w, acc[r]);
        }
    }
    #pragma unroll
    for (int r = 0; r < 8; r++)
        out[(size_t)(r0 + r) * 256 + d] = acc[r];
}

// ---------------------------------------------------------------------------
extern "C" void kernel_launch(void* const* d_in, const int* in_sizes, int n_in,
                              void* d_out, int out_size)
{
    const float* x   = (const float*)d_in[0];
    const float* q   = (const float*)d_in[1];
    const float* wks = (const float*)d_in[2];
    const float* wvs = (const float*)d_in[3];
    const float* wfc = (const float*)d_in[4];

    float* out  = (float*)d_out;
    float* hard = out + OUT_ELE;

    static bool attr_done = false;
    if (!attr_done) {
        cudaFuncSetAttribute(k_proj, cudaFuncAttributeMaxDynamicSharedMemorySize, SMEM_PROJ);
        cudaFuncSetAttribute(k_attn, cudaFuncAttributeMaxDynamicSharedMemorySize, SMEM_ATTN);
        cudaFuncSetAttribute(k_fc,   cudaFuncAttributeMaxDynamicSharedMemorySize, SMEM_FC);
        attr_done = true;
    }

    k_pack<<<129, 256>>>(q, wks, wvs);
    k_proj<<<1024, 256, SMEM_PROJ>>>(x);
    k_attn<<<2048, 256, SMEM_ATTN>>>(hard);
    k_fc<<<512, 256, SMEM_FC>>>(wfc, out);
}